// round 6
// baseline (speedup 1.0000x reference)
#include <cuda_runtime.h>
#include <cuda_bf16.h>

#define BATCH 16384
#define DIM   1024
#define DIM4  (DIM / 4)       // 256 float4 per row
#define NL    4

__device__ float g_D[NL];     // D_l = dot(c_l, W_l), c_l = sum_{j<l} b_j
__device__ float g_Csum[DIM]; // b0+b1+b2+b3

// ---------------------------------------------------------------------------
// Precompute: 1 CTA, 1024 threads, reads 32 KB. (~1 us, cheap graph node)
// ---------------------------------------------------------------------------
__global__ __launch_bounds__(DIM) void crossnet_precompute(
    const float* __restrict__ W, const float* __restrict__ b)
{
    int d = threadIdx.x;
    float b0 = b[d];
    float b1 = b[DIM + d];
    float b2 = b[2 * DIM + d];
    float b3 = b[3 * DIM + d];

    float c1 = b0;
    float c2 = c1 + b1;
    float c3 = c2 + b2;
    g_Csum[d] = c3 + b3;

    float p1 = c1 * W[DIM + d];
    float p2 = c2 * W[2 * DIM + d];
    float p3 = c3 * W[3 * DIM + d];

    #pragma unroll
    for (int o = 16; o; o >>= 1) {
        p1 += __shfl_xor_sync(0xFFFFFFFFu, p1, o);
        p2 += __shfl_xor_sync(0xFFFFFFFFu, p2, o);
        p3 += __shfl_xor_sync(0xFFFFFFFFu, p3, o);
    }

    __shared__ float sm[3][32];
    int warp = threadIdx.x >> 5;
    int lane = threadIdx.x & 31;
    if (lane == 0) { sm[0][warp] = p1; sm[1][warp] = p2; sm[2][warp] = p3; }
    __syncthreads();
    if (warp == 0) {
        float q1 = sm[0][lane];
        float q2 = sm[1][lane];
        float q3 = sm[2][lane];
        #pragma unroll
        for (int o = 16; o; o >>= 1) {
            q1 += __shfl_xor_sync(0xFFFFFFFFu, q1, o);
            q2 += __shfl_xor_sync(0xFFFFFFFFu, q2, o);
            q3 += __shfl_xor_sync(0xFFFFFFFFu, q3, o);
        }
        if (lane == 0) {
            g_D[0] = 0.0f; g_D[1] = q1; g_D[2] = q2; g_D[3] = q3;
        }
    }
}

// ---------------------------------------------------------------------------
// Main kernel (R4 structure + forced 3 CTAs/SM).
//  - W (16 KB) + Csum (4 KB) in shared: LDG queue holds only x0 traffic.
//  - 2 rows/warp, all 16 x loads front-batched into registers.
//  - Plain loads on x0 (preserve L2 residency), __stcs streaming stores.
// ---------------------------------------------------------------------------
#define TPB 256
#define WARPS_PER_CTA 8
#define ROWS_PER_CTA (WARPS_PER_CTA * 2)   // 16
#define GRID (BATCH / ROWS_PER_CTA)        // 1024

__device__ __forceinline__ float dot4(float4 x, float4 w, float acc) {
    return fmaf(x.x, w.x, fmaf(x.y, w.y, fmaf(x.z, w.z, fmaf(x.w, w.w, acc))));
}

__global__ __launch_bounds__(TPB, 3) void crossnet_main(
    const float4* __restrict__ x0,
    const float4* __restrict__ W4,
    float4* __restrict__ out)
{
    __shared__ float4 sW[NL][DIM4];   // 16 KB
    __shared__ float4 sC[DIM4];       //  4 KB
    __shared__ float  sD[NL];

    const int tid  = threadIdx.x;
    const int warp = tid >> 5;
    const int lane = tid & 31;

    // one-time smem fill (DIM4 == TPB)
    sW[0][tid] = W4[tid];
    sW[1][tid] = W4[DIM4 + tid];
    sW[2][tid] = W4[2 * DIM4 + tid];
    sW[3][tid] = W4[3 * DIM4 + tid];
    sC[tid]    = ((const float4*)g_Csum)[tid];
    if (tid < NL) sD[tid] = g_D[tid];
    __syncthreads();

    const int rowA = (blockIdx.x * WARPS_PER_CTA + warp) * 2;
    const float4* __restrict__ xa = x0 + (size_t)rowA * DIM4;
    const float4* __restrict__ xb = xa + DIM4;

    // ---- front-batch all 16 x loads (DRAM-miss stream) ----
    float4 xA[8], xB[8];
    #pragma unroll
    for (int k = 0; k < 8; k++) {
        const int i = k * 32 + lane;
        xA[k] = xa[i];
        xB[k] = xb[i];
    }

    // ---- dot products vs smem W ----
    float uA0 = 0.f, uA1 = 0.f, uA2 = 0.f, uA3 = 0.f;
    float uB0 = 0.f, uB1 = 0.f, uB2 = 0.f, uB3 = 0.f;
    #pragma unroll
    for (int k = 0; k < 8; k++) {
        const int i = k * 32 + lane;
        float4 w0 = sW[0][i];
        float4 w1 = sW[1][i];
        float4 w2 = sW[2][i];
        float4 w3 = sW[3][i];
        uA0 = dot4(xA[k], w0, uA0);  uB0 = dot4(xB[k], w0, uB0);
        uA1 = dot4(xA[k], w1, uA1);  uB1 = dot4(xB[k], w1, uB1);
        uA2 = dot4(xA[k], w2, uA2);  uB2 = dot4(xB[k], w2, uB2);
        uA3 = dot4(xA[k], w3, uA3);  uB3 = dot4(xB[k], w3, uB3);
    }

    #pragma unroll
    for (int o = 16; o; o >>= 1) {
        uA0 += __shfl_xor_sync(0xFFFFFFFFu, uA0, o);
        uA1 += __shfl_xor_sync(0xFFFFFFFFu, uA1, o);
        uA2 += __shfl_xor_sync(0xFFFFFFFFu, uA2, o);
        uA3 += __shfl_xor_sync(0xFFFFFFFFu, uA3, o);
        uB0 += __shfl_xor_sync(0xFFFFFFFFu, uB0, o);
        uB1 += __shfl_xor_sync(0xFFFFFFFFu, uB1, o);
        uB2 += __shfl_xor_sync(0xFFFFFFFFu, uB2, o);
        uB3 += __shfl_xor_sync(0xFFFFFFFFu, uB3, o);
    }

    const float D1 = sD[1], D2 = sD[2], D3 = sD[3];

    float aA = 1.0f + uA0;                 // D0 == 0
    aA += fmaf(aA, uA1, D1);
    aA += fmaf(aA, uA2, D2);
    aA += fmaf(aA, uA3, D3);

    float aB = 1.0f + uB0;
    aB += fmaf(aB, uB1, D1);
    aB += fmaf(aB, uB2, D2);
    aB += fmaf(aB, uB3, D3);

    // ---- write: out = a * x0 + Csum ----
    float4* __restrict__ oa = out + (size_t)rowA * DIM4;
    float4* __restrict__ ob = oa + DIM4;

    #pragma unroll
    for (int k = 0; k < 8; k++) {
        const int i = k * 32 + lane;
        float4 c = sC[i];
        float4 rA, rB;
        rA.x = fmaf(aA, xA[k].x, c.x); rA.y = fmaf(aA, xA[k].y, c.y);
        rA.z = fmaf(aA, xA[k].z, c.z); rA.w = fmaf(aA, xA[k].w, c.w);
        rB.x = fmaf(aB, xB[k].x, c.x); rB.y = fmaf(aB, xB[k].y, c.y);
        rB.z = fmaf(aB, xB[k].z, c.z); rB.w = fmaf(aB, xB[k].w, c.w);
        __stcs(&oa[i], rA);
        __stcs(&ob[i], rB);
    }
}

extern "C" void kernel_launch(void* const* d_in, const int* in_sizes, int n_in,
                              void* d_out, int out_size)
{
    const float* x0 = (const float*)d_in[0];   // [16384, 1024]
    const float* W  = (const float*)d_in[1];   // [4, 1024]
    const float* b  = (const float*)d_in[2];   // [4, 1024]
    float* out      = (float*)d_out;           // [16384, 1024]

    crossnet_precompute<<<1, DIM>>>(W, b);
    crossnet_main<<<GRID, TPB>>>((const float4*)x0, (const float4*)W,
                                 (float4*)out);
}

// round 8
// speedup vs baseline: 1.1854x; 1.1854x over previous
#include <cuda_runtime.h>
#include <cuda_bf16.h>
#include <cstdint>

#define BATCH 16384
#define DIM   1024
#define DIM4  (DIM / 4)        // 256 float4 per row
#define NL    4

#define TPB        256
#define TILE_ROWS  16
#define TILE_F4    (TILE_ROWS * DIM4)      // 4096 float4 = 64 KB
#define NBUF       2
#define GRID_MAIN  148                     // persistent, 1 CTA/SM
#define TOTAL_TILES (BATCH / TILE_ROWS)    // 1024

// dynamic smem: [ buf0 | buf1 | sW (16KB) | sC (4KB) | sD (16B) ]
#define SMEM_TOTAL (NBUF * TILE_F4 * 16 + NL * DIM4 * 16 + DIM4 * 16 + 16)

__device__ float g_D[NL];      // D_l = dot(c_l, W_l), c_l = sum_{j<l} b_j
__device__ float g_Csum[DIM];  // b0+b1+b2+b3

// ---------------------------------------------------------------------------
// Precompute: 1 CTA, 1024 threads, reads 32 KB.
// ---------------------------------------------------------------------------
__global__ __launch_bounds__(DIM) void crossnet_precompute(
    const float* __restrict__ W, const float* __restrict__ b)
{
    int d = threadIdx.x;
    float b0 = b[d];
    float b1 = b[DIM + d];
    float b2 = b[2 * DIM + d];
    float b3 = b[3 * DIM + d];

    float c1 = b0;
    float c2 = c1 + b1;
    float c3 = c2 + b2;
    g_Csum[d] = c3 + b3;

    float p1 = c1 * W[DIM + d];
    float p2 = c2 * W[2 * DIM + d];
    float p3 = c3 * W[3 * DIM + d];

    #pragma unroll
    for (int o = 16; o; o >>= 1) {
        p1 += __shfl_xor_sync(0xFFFFFFFFu, p1, o);
        p2 += __shfl_xor_sync(0xFFFFFFFFu, p2, o);
        p3 += __shfl_xor_sync(0xFFFFFFFFu, p3, o);
    }
    __shared__ float sm[3][32];
    int warp = threadIdx.x >> 5;
    int lane = threadIdx.x & 31;
    if (lane == 0) { sm[0][warp] = p1; sm[1][warp] = p2; sm[2][warp] = p3; }
    __syncthreads();
    if (warp == 0) {
        float q1 = sm[0][lane];
        float q2 = sm[1][lane];
        float q3 = sm[2][lane];
        #pragma unroll
        for (int o = 16; o; o >>= 1) {
            q1 += __shfl_xor_sync(0xFFFFFFFFu, q1, o);
            q2 += __shfl_xor_sync(0xFFFFFFFFu, q2, o);
            q3 += __shfl_xor_sync(0xFFFFFFFFu, q3, o);
        }
        if (lane == 0) {
            g_D[0] = 0.0f; g_D[1] = q1; g_D[2] = q2; g_D[3] = q3;
        }
    }
}

// ---------------------------------------------------------------------------
// cp.async helpers
// ---------------------------------------------------------------------------
__device__ __forceinline__ void cp_async16(float4* smem_dst, const float4* gsrc) {
    unsigned int s = (unsigned int)__cvta_generic_to_shared(smem_dst);
    asm volatile("cp.async.cg.shared.global [%0], [%1], 16;" :: "r"(s), "l"(gsrc));
}
__device__ __forceinline__ void cp_commit() {
    asm volatile("cp.async.commit_group;");
}

__device__ __forceinline__ void prefetch_tile(float4* dst, const float4* src, int tid) {
    #pragma unroll
    for (int j = 0; j < TILE_F4 / TPB; j++) {      // 16 x 16B per thread
        int idx = j * TPB + tid;
        cp_async16(dst + idx, src + idx);
    }
    cp_commit();
}

__device__ __forceinline__ float dot4(float4 x, float4 w, float acc) {
    return fmaf(x.x, w.x, fmaf(x.y, w.y, fmaf(x.z, w.z, fmaf(x.w, w.w, acc))));
}

// ---------------------------------------------------------------------------
// Main: persistent CTAs; x0 streamed via cp.async double buffer.
// Per tile: 8 warps x 2 rows; dot vs smem W; recurrence; streaming stores.
// ---------------------------------------------------------------------------
__global__ __launch_bounds__(TPB) void crossnet_main(
    const float4* __restrict__ x0,
    const float4* __restrict__ W4,
    float4* __restrict__ out)
{
    extern __shared__ float4 dsm[];
    float4* buf = dsm;                          // NBUF * TILE_F4
    float4* sW  = dsm + NBUF * TILE_F4;         // NL * DIM4
    float4* sC  = sW + NL * DIM4;               // DIM4
    float*  sD  = (float*)(sC + DIM4);          // NL

    const int tid  = threadIdx.x;
    const int warp = tid >> 5;
    const int lane = tid & 31;
    const int bid  = blockIdx.x;

    // tiles this CTA owns: tt = bid + n*GRID_MAIN
    const int my_n = (TOTAL_TILES - bid + GRID_MAIN - 1) / GRID_MAIN;

    // ---- prologue: kick off first two tile fetches, then fill sW/sC/sD ----
    if (my_n > 0)
        prefetch_tile(buf, x0 + (size_t)bid * TILE_F4, tid);
    if (my_n > 1)
        prefetch_tile(buf + TILE_F4, x0 + (size_t)(bid + GRID_MAIN) * TILE_F4, tid);

    sW[tid]            = W4[tid];
    sW[DIM4 + tid]     = W4[DIM4 + tid];
    sW[2 * DIM4 + tid] = W4[2 * DIM4 + tid];
    sW[3 * DIM4 + tid] = W4[3 * DIM4 + tid];
    sC[tid]            = ((const float4*)g_Csum)[tid];
    if (tid < NL) sD[tid] = g_D[tid];

    for (int n = 0; n < my_n; n++) {
        // tile n's group is complete when at most (remaining groups) pending
        if (n + 1 < my_n) asm volatile("cp.async.wait_group 1;");
        else              asm volatile("cp.async.wait_group 0;");
        __syncthreads();   // buffer + (first iter) sW/sC/sD visible to all

        const float4* tb = buf + (n & 1) * TILE_F4;
        const int rloc = warp * 2;
        const float4* __restrict__ xa = tb + rloc * DIM4;
        const float4* __restrict__ xb = xa + DIM4;

        // x into registers (LDS, conflict-free)
        float4 xA[8], xB[8];
        #pragma unroll
        for (int k = 0; k < 8; k++) {
            const int i = k * 32 + lane;
            xA[k] = xa[i];
            xB[k] = xb[i];
        }

        float uA0 = 0.f, uA1 = 0.f, uA2 = 0.f, uA3 = 0.f;
        float uB0 = 0.f, uB1 = 0.f, uB2 = 0.f, uB3 = 0.f;
        #pragma unroll
        for (int k = 0; k < 8; k++) {
            const int i = k * 32 + lane;
            float4 w0 = sW[i];
            float4 w1 = sW[DIM4 + i];
            float4 w2 = sW[2 * DIM4 + i];
            float4 w3 = sW[3 * DIM4 + i];
            uA0 = dot4(xA[k], w0, uA0);  uB0 = dot4(xB[k], w0, uB0);
            uA1 = dot4(xA[k], w1, uA1);  uB1 = dot4(xB[k], w1, uB1);
            uA2 = dot4(xA[k], w2, uA2);  uB2 = dot4(xB[k], w2, uB2);
            uA3 = dot4(xA[k], w3, uA3);  uB3 = dot4(xB[k], w3, uB3);
        }

        #pragma unroll
        for (int o = 16; o; o >>= 1) {
            uA0 += __shfl_xor_sync(0xFFFFFFFFu, uA0, o);
            uA1 += __shfl_xor_sync(0xFFFFFFFFu, uA1, o);
            uA2 += __shfl_xor_sync(0xFFFFFFFFu, uA2, o);
            uA3 += __shfl_xor_sync(0xFFFFFFFFu, uA3, o);
            uB0 += __shfl_xor_sync(0xFFFFFFFFu, uB0, o);
            uB1 += __shfl_xor_sync(0xFFFFFFFFu, uB1, o);
            uB2 += __shfl_xor_sync(0xFFFFFFFFu, uB2, o);
            uB3 += __shfl_xor_sync(0xFFFFFFFFu, uB3, o);
        }

        const float D1 = sD[1], D2 = sD[2], D3 = sD[3];

        float aA = 1.0f + uA0;                 // D0 == 0
        aA += fmaf(aA, uA1, D1);
        aA += fmaf(aA, uA2, D2);
        aA += fmaf(aA, uA3, D3);

        float aB = 1.0f + uB0;
        aB += fmaf(aB, uB1, D1);
        aB += fmaf(aB, uB2, D2);
        aB += fmaf(aB, uB3, D3);

        const int tt = bid + n * GRID_MAIN;
        const size_t rowA = (size_t)tt * TILE_ROWS + rloc;
        float4* __restrict__ oa = out + rowA * DIM4;
        float4* __restrict__ ob = oa + DIM4;

        #pragma unroll
        for (int k = 0; k < 8; k++) {
            const int i = k * 32 + lane;
            float4 c = sC[i];
            float4 rA, rB;
            rA.x = fmaf(aA, xA[k].x, c.x); rA.y = fmaf(aA, xA[k].y, c.y);
            rA.z = fmaf(aA, xA[k].z, c.z); rA.w = fmaf(aA, xA[k].w, c.w);
            rB.x = fmaf(aB, xB[k].x, c.x); rB.y = fmaf(aB, xB[k].y, c.y);
            rB.z = fmaf(aB, xB[k].z, c.z); rB.w = fmaf(aB, xB[k].w, c.w);
            __stcs(&oa[i], rA);
            __stcs(&ob[i], rB);
        }

        __syncthreads();   // everyone done reading buf[n&1] before refill

        if (n + NBUF < my_n) {
            const int nt = bid + (n + NBUF) * GRID_MAIN;
            prefetch_tile(buf + (n & 1) * TILE_F4,
                          x0 + (size_t)nt * TILE_F4, tid);
        }
    }
}

extern "C" void kernel_launch(void* const* d_in, const int* in_sizes, int n_in,
                              void* d_out, int out_size)
{
    const float* x0 = (const float*)d_in[0];   // [16384, 1024]
    const float* W  = (const float*)d_in[1];   // [4, 1024]
    const float* b  = (const float*)d_in[2];   // [4, 1024]
    float* out      = (float*)d_out;           // [16384, 1024]

    cudaFuncSetAttribute(crossnet_main,
                         cudaFuncAttributeMaxDynamicSharedMemorySize,
                         SMEM_TOTAL);

    crossnet_precompute<<<1, DIM>>>(W, b);
    crossnet_main<<<GRID_MAIN, TPB, SMEM_TOTAL>>>(
        (const float4*)x0, (const float4*)W, (float4*)out);
}